// round 9
// baseline (speedup 1.0000x reference)
#include <cuda_runtime.h>
#include <math.h>

#define NROWS 16384
#define Tt 15
#define EPSg 1e-10f

typedef unsigned long long u64t;

// ---------------- scratch ----------------
__device__ float g_h[NROWS*64];
__device__ float g_q[NROWS*64];
__device__ float g_k[NROWS*64];
__device__ float g_v[NROWS*64];
// paired layout: [row][ (gate*32+c)*2 + h ]  value = X[row][gate*64 + c + 32*h]
__device__ float g_Gf [NROWS*192];
__device__ float g_Cbf[NROWS*192];
__device__ float g_Gb [NROWS*192];
__device__ float g_Cbb[NROWS*192];
__device__ float g_lf[NROWS*2*Tt];
__device__ float g_lb[NROWS*2*Tt];
// packed cell weights: float4 at ((dd*3+gate)*32+c):
//   ( Wih[(gate*64+c)*64+dd], Wih[(gate*64+c+32)*64+dd],
//     Whh[(gate*64+c)*64+dd], Whh[(gate*64+c+32)*64+dd] )
__device__ float g_Wc[64*3*32*4];

__device__ __forceinline__ float sigm(float x){ return 1.0f/(1.0f+__expf(-x)); }
__device__ __forceinline__ float tanh_(float x){ return 2.0f/(1.0f+__expf(-2.0f*x)) - 1.0f; }

__device__ __forceinline__ u64t pk(float x, float y){
    u64t r; asm("mov.b64 %0,{%1,%2};" : "=l"(r) : "f"(x), "f"(y)); return r;
}
__device__ __forceinline__ float2 up(u64t v){
    float2 r; asm("mov.b64 {%0,%1},%2;" : "=f"(r.x), "=f"(r.y) : "l"(v)); return r;
}
__device__ __forceinline__ void fma2(u64t& d, u64t a, u64t b){
    asm("fma.rn.f32x2 %0,%1,%2,%0;" : "+l"(d) : "l"(a), "l"(b));
}

// pairpos for proj micro-kernel weight tiles (16-lane pairing)
__device__ __forceinline__ int pairpos64(int d, int c){
    return ((d<<5) + (((c>>5)&1)<<4) + (c&15))*2 + ((c>>4)&1);
}

// =====================================================================
// K0: encoder. h_enc = relu(obs @ W_enc + b_enc) -> g_h
// =====================================================================
__global__ __launch_bounds__(256)
void k_enc(const float* __restrict__ obs,
           const float* __restrict__ W_enc, const float* __restrict__ b_enc)
{
    extern __shared__ float sm[];
    float* Os = sm;                 // 64*68
    float* Wt = sm + 64*68;         // 4096 paired
    const u64t* Wt64 = (const u64t*)Wt;
    const int tid = threadIdx.x;
    const int rbase = blockIdx.x * 64;
    const int ty = tid >> 4, tx = tid & 15;
    const int r0 = ty * 4;
    int dcol[4];
    #pragma unroll
    for (int k=0;k<4;k++) dcol[k] = tx + ((k>>1)<<5) + ((k&1)<<4);

    for (int idx = tid; idx < 4096; idx += 256) {
        int r = idx >> 6, c = idx & 63;
        Os[r*68+c] = obs[(rbase+r)*64 + c];
        Wt[pairpos64(r, c)] = W_enc[idx];
    }
    __syncthreads();

    u64t acc[4][2];
    #pragma unroll
    for (int i=0;i<4;i++){ acc[i][0]=0ull; acc[i][1]=0ull; }
    for (int dd=0; dd<64; ++dd){
        u64t pa[4];
        #pragma unroll
        for (int i=0;i<4;i++){ float a=Os[(r0+i)*68+dd]; pa[i]=pk(a,a); }
        #pragma unroll
        for (int p=0;p<2;p++){
            u64t w = Wt64[dd*32 + p*16 + tx];
            #pragma unroll
            for (int i=0;i<4;i++) fma2(acc[i][p], pa[i], w);
        }
    }
    #pragma unroll
    for (int i=0;i<4;i++)
        #pragma unroll
        for (int p=0;p<2;p++){
            float2 v = up(acc[i][p]);
            int d0 = dcol[2*p], d1 = dcol[2*p+1];
            g_h[(rbase+r0+i)*64 + d0] = fmaxf(v.x + b_enc[d0], 0.0f);
            g_h[(rbase+r0+i)*64 + d1] = fmaxf(v.y + b_enc[d1], 0.0f);
        }
}

// =====================================================================
// K0b: pack cell weights into g_Wc (float4 per (dd,gate,lane))
// =====================================================================
__global__ __launch_bounds__(256)
void k_packW(const float* __restrict__ Wih_c, const float* __restrict__ Whh_c)
{
    int idx = blockIdx.x * 256 + threadIdx.x;   // 6144 float4 slots
    if (idx >= 6144) return;
    int dd = idx / 96;
    int rem = idx - dd*96;
    int gate = rem >> 5;
    int c = rem & 31;
    float4 w;
    w.x = Wih_c[(gate*64 + c     )*64 + dd];
    w.y = Wih_c[(gate*64 + c + 32)*64 + dd];
    w.z = Whh_c[(gate*64 + c     )*64 + dd];
    w.w = Whh_c[(gate*64 + c + 32)*64 + dd];
    ((float4*)g_Wc)[idx] = w;
}

// =====================================================================
// K1: projections. grid (256 tiles, 5 groups), 3 segments per block.
// =====================================================================
__global__ __launch_bounds__(256)
void k_proj2(const float* __restrict__ Wq, const float* __restrict__ Wk,
             const float* __restrict__ Wv, const float* __restrict__ b_v,
             const float* __restrict__ Wih_f, const float* __restrict__ bih_f,
             const float* __restrict__ Wih_b, const float* __restrict__ bih_b)
{
    extern __shared__ float sm[];
    float* Hs = sm;                 // 64*68
    float* Wt = sm + 64*68;         // 4096 paired
    const u64t* Wt64 = (const u64t*)Wt;
    const int tid = threadIdx.x;
    const int rbase = blockIdx.x * 64;
    const int gy = blockIdx.y;
    const int ty = tid >> 4, tx = tid & 15;
    const int r0 = ty * 4;
    int dcol[4];
    #pragma unroll
    for (int k=0;k<4;k++) dcol[k] = tx + ((k>>1)<<5) + ((k&1)<<4);

    for (int idx = tid; idx < 4096; idx += 256) {
        int r = idx >> 6, c = idx & 63;
        Hs[r*68+c] = g_h[(rbase+r)*64 + c];
    }

    for (int j = 0; j < 3; ++j){
        const float* Wsrc=nullptr; const float* bias=nullptr;
        float* dst=nullptr; int mode; int doRelu=0; int gate=j;
        if (gy==0){
            mode=0;
            if (j==0){ Wsrc=Wq; dst=g_q; }
            else if (j==1){ Wsrc=Wk; dst=g_k; }
            else { Wsrc=Wv; dst=g_v; bias=b_v; doRelu=1; }
        } else if (gy==1){ mode=1; Wsrc=Wih_f; dst=g_Cbf; bias=bih_f; }
        else if   (gy==2){ mode=2; Wsrc=Wih_f; dst=g_Gf; }
        else if   (gy==3){ mode=1; Wsrc=Wih_b; dst=g_Cbb; bias=bih_b; }
        else              { mode=2; Wsrc=Wih_b; dst=g_Gb; }
        const int colBase = gate*64;

        __syncthreads();
        for (int idx = tid; idx < 4096; idx += 256){
            int hi = idx >> 6, lo = idx & 63;
            if (mode==0) Wt[pairpos64(hi, lo)] = Wsrc[idx];
            else {
                int off = (colBase+hi)*128 + lo + (mode==2 ? 64 : 0);
                Wt[pairpos64(lo, hi)] = Wsrc[off];
            }
        }
        __syncthreads();

        u64t acc[4][2];
        #pragma unroll
        for (int i=0;i<4;i++){ acc[i][0]=0ull; acc[i][1]=0ull; }
        for (int dd=0; dd<64; ++dd){
            u64t pa[4];
            #pragma unroll
            for (int i=0;i<4;i++){ float a=Hs[(r0+i)*68+dd]; pa[i]=pk(a,a); }
            #pragma unroll
            for (int p=0;p<2;p++){
                u64t w = Wt64[dd*32 + p*16 + tx];
                #pragma unroll
                for (int i=0;i<4;i++) fma2(acc[i][p], pa[i], w);
            }
        }

        if (mode==0){
            #pragma unroll
            for (int i=0;i<4;i++)
                #pragma unroll
                for (int p=0;p<2;p++){
                    float2 v = up(acc[i][p]);
                    #pragma unroll
                    for (int h=0;h<2;h++){
                        int d = dcol[2*p+h];
                        float vv = (h ? v.y : v.x) + (bias ? bias[d] : 0.0f);
                        if (doRelu) vv = fmaxf(vv, 0.0f);
                        dst[(rbase+r0+i)*64 + d] = vv;
                    }
                }
        } else {
            float b0=0.f,b1=0.f,b2=0.f,b3=0.f;
            if (bias){
                b0=bias[colBase+tx]; b1=bias[colBase+tx+16];
                b2=bias[colBase+tx+32]; b3=bias[colBase+tx+48];
            }
            u64t* dst64 = (u64t*)dst;
            #pragma unroll
            for (int i=0;i<4;i++){
                float2 v0 = up(acc[i][0]);   // cols tx, tx+16
                float2 v1 = up(acc[i][1]);   // cols tx+32, tx+48
                int row = rbase + r0 + i;
                dst64[row*96 + gate*32 + tx]      = pk(v0.x + b0, v1.x + b2);
                dst64[row*96 + gate*32 + tx + 16] = pk(v0.y + b1, v1.y + b3);
            }
        }
    }
}

// =====================================================================
// K2: both GRU directions. 512 blocks x 256 threads, occ 2.
// Scalar FFMA mainloop. Warp owns 8 rows; lane owns cols (lane, lane+32).
// =====================================================================
__global__ __launch_bounds__(256,2)
void k_gru(const float* __restrict__ Whh_f, const float* __restrict__ bhh_f,
           const float* __restrict__ Whh_b, const float* __restrict__ bhh_b,
           const float* __restrict__ W_hard)
{
    extern __shared__ float sm[];
    float*  Wp  = sm;                 // 12288 floats (paired)
    float*  hs  = sm + 12288;         // 64*68 floats
    const float2* Wp2 = (const float2*)Wp;
    const int tid  = threadIdx.x;
    const int wid  = tid >> 5;
    const int lane = tid & 31;
    const int fwd = (blockIdx.x < 256);
    const int rbase = (blockIdx.x & 255) * 64;
    const int r0 = wid * 8;
    const float2* G2  = (const float2*)(fwd ? g_Gf  : g_Gb);
    const float2* Cb2 = (const float2*)(fwd ? g_Cbf : g_Cbb);
    const float* Whh   = fwd ? Whh_f : Whh_b;
    const float* bhh   = fwd ? bhh_f : bhh_b;
    float* lout = fwd ? g_lf : g_lb;

    for (int i = tid; i < 12288; i += 256){
        int gd = i >> 6, dd = i & 63;
        int g = gd >> 6, cc = gd & 63;
        int c = cc & 31, h = cc >> 5;
        Wp[(((dd*3 + g)*32 + c) << 1) + h] = Whh[i];
    }
    for (int i = tid; i < 64*68; i += 256) hs[i] = 0.0f;

    float br_lo=bhh[lane],     br_hi=bhh[lane+32];
    float bz_lo=bhh[64+lane],  bz_hi=bhh[96+lane];
    float bn_lo=bhh[128+lane], bn_hi=bhh[160+lane];
    int wb = fwd ? 0 : 64;
    float w0_lo=W_hard[(wb+lane)*2],    w0_hi=W_hard[(wb+lane+32)*2];
    float w1_lo=W_hard[(wb+lane)*2+1],  w1_hi=W_hard[(wb+lane+32)*2+1];
    __syncthreads();

    for (int step=0; step<Tt; ++step){
        const int t = fwd ? step : (Tt-1-step);
        float2 aR[8], aZ[8], aN[8];
        #pragma unroll
        for (int i=0;i<8;i++){
            aR[i]=make_float2(0.f,0.f); aZ[i]=make_float2(0.f,0.f); aN[i]=make_float2(0.f,0.f);
        }

        if (step){
            #pragma unroll 2
            for (int dd=0; dd<64; dd+=2){
                float2 w00 = Wp2[(dd*3+0)*32 + lane];
                float2 w01 = Wp2[(dd*3+1)*32 + lane];
                float2 w02 = Wp2[(dd*3+2)*32 + lane];
                float2 w10 = Wp2[((dd+1)*3+0)*32 + lane];
                float2 w11 = Wp2[((dd+1)*3+1)*32 + lane];
                float2 w12 = Wp2[((dd+1)*3+2)*32 + lane];
                #pragma unroll
                for (int i=0;i<8;i++){
                    float2 a = *(const float2*)&hs[(r0+i)*68 + dd];  // broadcast
                    aR[i].x += a.x*w00.x; aR[i].y += a.x*w00.y;
                    aZ[i].x += a.x*w01.x; aZ[i].y += a.x*w01.y;
                    aN[i].x += a.x*w02.x; aN[i].y += a.x*w02.y;
                    aR[i].x += a.y*w10.x; aR[i].y += a.y*w10.y;
                    aZ[i].x += a.y*w11.x; aZ[i].y += a.y*w11.y;
                    aN[i].x += a.y*w12.x; aN[i].y += a.y*w12.y;
                }
            }
        }

        float l0[8], l1[8];
        #pragma unroll
        for (int i=0;i<8;i++){
            int rl = r0+i;
            int ii = rl & 15;
            int jl = (rl & 48) + t + (t>=ii ? 1 : 0);
            size_t rg = (size_t)(rbase + rl)*96;
            size_t jg = (size_t)(rbase + jl)*96;
            float2 c0 = Cb2[rg      + lane];
            float2 c1 = Cb2[rg + 32 + lane];
            float2 c2 = Cb2[rg + 64 + lane];
            float2 g0 = G2 [jg      + lane];
            float2 g1 = G2 [jg + 32 + lane];
            float2 g2 = G2 [jg + 64 + lane];
            float ho_lo = hs[rl*68 + lane];
            float ho_hi = hs[rl*68 + 32 + lane];
            float r_lo = sigm(c0.x + g0.x + aR[i].x + br_lo);
            float r_hi = sigm(c0.y + g0.y + aR[i].y + br_hi);
            float z_lo = sigm(c1.x + g1.x + aZ[i].x + bz_lo);
            float z_hi = sigm(c1.y + g1.y + aZ[i].y + bz_hi);
            float n_lo = tanh_(c2.x + g2.x + r_lo*(aN[i].x + bn_lo));
            float n_hi = tanh_(c2.y + g2.y + r_hi*(aN[i].y + bn_hi));
            float hv_lo = (1.0f - z_lo)*n_lo + z_lo*ho_lo;
            float hv_hi = (1.0f - z_hi)*n_hi + z_hi*ho_hi;
            hs[rl*68 + lane]      = hv_lo;
            hs[rl*68 + 32 + lane] = hv_hi;
            l0[i] = hv_lo*w0_lo + hv_hi*w0_hi;
            l1[i] = hv_lo*w1_lo + hv_hi*w1_hi;
        }
        #pragma unroll
        for (int off=16; off>=1; off>>=1){
            #pragma unroll
            for (int i=0;i<8;i++){
                l0[i] += __shfl_xor_sync(0xffffffffu, l0[i], off);
                l1[i] += __shfl_xor_sync(0xffffffffu, l1[i], off);
            }
        }
        #pragma unroll
        for (int i=0;i<8;i++){
            if (lane == i){
                ((u64t*)lout)[(size_t)(rbase + r0 + i)*Tt + t] = pk(l0[i], l1[i]);
            }
        }
    }
}

// =====================================================================
// K3: gumbel hard weights + attention + final GRU cell.
// 512 threads, 64 rows/block, 95KB smem -> 2 blocks/SM.
// Cell GEMM: scalar FFMA, warp owns 4 rows, lane owns cols (lane, lane+32),
// weights via LDG.128 from g_Wc (L1-resident, shared by all blocks).
// =====================================================================
__global__ __launch_bounds__(512,2)
void k_attn_cell(const float* __restrict__ hidden,
                 const float* __restrict__ gum,
                 const float* __restrict__ b_hard,
                 const float* __restrict__ bih_c, const float* __restrict__ bhh_c,
                 float* __restrict__ out)
{
    extern __shared__ float sm[];
    float* qs  = sm;                 // 64*68
    float* ks_ = qs  + 64*68;
    float* vs  = ks_ + 64*68;
    float* hds = vs  + 64*68;
    float* xs  = hds + 64*68;
    float* hw  = xs  + 64*68;        // 64*16
    float* sc  = hw  + 64*16;        // 64*16
    const int tid = threadIdx.x;
    const int rbase = blockIdx.x * 64;

    // vectorized loads: 64 rows x 16 float4 per array
    for (int idx=tid; idx<1024; idx+=512){
        int r=idx>>4, c4=idx&15;
        ((float4*)qs )[r*17+c4] = ((const float4*)g_q)[(rbase+r)*16+c4];
        ((float4*)ks_)[r*17+c4] = ((const float4*)g_k)[(rbase+r)*16+c4];
        ((float4*)vs )[r*17+c4] = ((const float4*)g_v)[(rbase+r)*16+c4];
        ((float4*)hds)[r*17+c4] = ((const float4*)hidden)[(rbase+r)*16+c4];
    }
    {
        const float bh0 = b_hard[0], bh1 = b_hard[1];
        for (int idx=tid; idx<64*Tt; idx+=512){
            int r=idx/Tt, t=idx-r*Tt;
            int row = rbase + r;
            float L0 = g_lf[row*(2*Tt)+2*t]   + g_lb[row*(2*Tt)+2*t]   + bh0;
            float L1 = g_lf[row*(2*Tt)+2*t+1] + g_lb[row*(2*Tt)+2*t+1] + bh1;
            int gi = (row*Tt + t)*2;
            float u0 = gum[gi], u1 = gum[gi+1];
            float gg0 = -logf(-logf(u0+EPSg)+EPSg);
            float gg1 = -logf(-logf(u1+EPSg)+EPSg);
            float dlt = ((L1+gg1)-(L0+gg0)) * 100.0f;   // /TAU
            hw[r*16+t] = 1.0f/(1.0f+__expf(-dlt));
        }
    }
    __syncthreads();

    {   // scores: 8 threads/row, 2 t's each
        int rp = tid>>3, qq = tid&7;
        #pragma unroll
        for (int s2=0; s2<2; ++s2){
            int t = qq + 8*s2;
            if (t < Tt){
                int ii = rp & 15;
                int jl = (rp & 48) + t + (t>=ii ? 1 : 0);
                float dot=0.f;
                #pragma unroll 8
                for (int d=0; d<64; ++d) dot += qs[rp*68+d]*ks_[jl*68+d];
                sc[rp*16+t] = dot*0.125f;
            }
        }
    }
    __syncthreads();
    if (tid < 64){
        int r=tid;
        float m=-1e30f;
        #pragma unroll
        for (int t=0;t<Tt;t++) m = fmaxf(m, sc[r*16+t]);
        float e[Tt]; float ssum=0.f;
        #pragma unroll
        for (int t=0;t<Tt;t++){ e[t]=__expf(sc[r*16+t]-m); ssum+=e[t]; }
        float inv = 1.0f/ssum;
        #pragma unroll
        for (int t=0;t<Tt;t++) sc[r*16+t] = e[t]*inv*hw[r*16+t];
    }
    __syncthreads();
    for (int idx=tid; idx<4096; idx+=512){
        int r=idx>>6, d=idx&63;
        int ii = r & 15, rb2 = r & 48;
        float x=0.f;
        #pragma unroll
        for (int t=0;t<Tt;t++){
            int jl = rb2 + t + (t>=ii ? 1 : 0);
            x += vs[jl*68+d]*sc[r*16+t];
        }
        xs[r*68+d]=x;
    }
    __syncthreads();

    // final GRU cell: warp owns 4 rows, lane owns cols (lane, lane+32)
    const int wid = tid >> 5, lane = tid & 31;
    const int r0 = wid * 4;
    const float4* Wc4 = (const float4*)g_Wc;

    float2 aR[4], aZ[4], aI[4], aH[4];
    #pragma unroll
    for (int i=0;i<4;i++){
        aR[i]=make_float2(0.f,0.f); aZ[i]=make_float2(0.f,0.f);
        aI[i]=make_float2(0.f,0.f); aH[i]=make_float2(0.f,0.f);
    }
    #pragma unroll 2
    for (int dd=0; dd<64; ++dd){
        float4 w0 = Wc4[(dd*3+0)*32 + lane];
        float4 w1 = Wc4[(dd*3+1)*32 + lane];
        float4 w2 = Wc4[(dd*3+2)*32 + lane];
        #pragma unroll
        for (int i=0;i<4;i++){
            float x = xs [(r0+i)*68 + dd];
            float h = hds[(r0+i)*68 + dd];
            aR[i].x += x*w0.x + h*w0.z;  aR[i].y += x*w0.y + h*w0.w;
            aZ[i].x += x*w1.x + h*w1.z;  aZ[i].y += x*w1.y + h*w1.w;
            aI[i].x += x*w2.x;           aI[i].y += x*w2.y;
            aH[i].x += h*w2.z;           aH[i].y += h*w2.w;
        }
    }
    float brc_lo = bih_c[lane]      + bhh_c[lane];
    float brc_hi = bih_c[lane+32]   + bhh_c[lane+32];
    float bzc_lo = bih_c[64+lane]   + bhh_c[64+lane];
    float bzc_hi = bih_c[96+lane]   + bhh_c[96+lane];
    float bni_lo = bih_c[128+lane],  bni_hi = bih_c[160+lane];
    float bnh_lo = bhh_c[128+lane],  bnh_hi = bhh_c[160+lane];
    #pragma unroll
    for (int i=0;i<4;i++){
        int rl = r0+i;
        float ho_lo = hds[rl*68 + lane];
        float ho_hi = hds[rl*68 + 32 + lane];
        float r_lo = sigm(aR[i].x + brc_lo);
        float r_hi = sigm(aR[i].y + brc_hi);
        float z_lo = sigm(aZ[i].x + bzc_lo);
        float z_hi = sigm(aZ[i].y + bzc_hi);
        float n_lo = tanh_(aI[i].x + bni_lo + r_lo*(aH[i].x + bnh_lo));
        float n_hi = tanh_(aI[i].y + bni_hi + r_hi*(aH[i].y + bnh_hi));
        out[(rbase+rl)*64 + lane]      = (1.0f - z_lo)*n_lo + z_lo*ho_lo;
        out[(rbase+rl)*64 + 32 + lane] = (1.0f - z_hi)*n_hi + z_hi*ho_hi;
    }
}

// =====================================================================
extern "C" void kernel_launch(void* const* d_in, const int* in_sizes, int n_in,
                              void* d_out, int out_size)
{
    (void)in_sizes; (void)n_in; (void)out_size;
    const float* obs    = (const float*)d_in[0];
    const float* hidden = (const float*)d_in[1];
    const float* gum    = (const float*)d_in[2];
    const float* W_enc  = (const float*)d_in[3];
    const float* b_enc  = (const float*)d_in[4];
    const float* Wih_f  = (const float*)d_in[5];
    const float* Whh_f  = (const float*)d_in[6];
    const float* bih_f  = (const float*)d_in[7];
    const float* bhh_f  = (const float*)d_in[8];
    const float* Wih_b  = (const float*)d_in[9];
    const float* Whh_b  = (const float*)d_in[10];
    const float* bih_b  = (const float*)d_in[11];
    const float* bhh_b  = (const float*)d_in[12];
    const float* W_hard = (const float*)d_in[13];
    const float* b_hard = (const float*)d_in[14];
    const float* Wq     = (const float*)d_in[15];
    const float* Wk     = (const float*)d_in[16];
    const float* Wv     = (const float*)d_in[17];
    const float* b_v    = (const float*)d_in[18];
    const float* Wih_c  = (const float*)d_in[19];
    const float* Whh_c  = (const float*)d_in[20];
    const float* bih_c  = (const float*)d_in[21];
    const float* bhh_c  = (const float*)d_in[22];
    float* out = (float*)d_out;

    const int sm0 = (64*68 + 4096) * (int)sizeof(float);                    // 33,792 B
    const int sm1 = (64*68 + 4096) * (int)sizeof(float);                    // 33,792 B
    const int sm2 = (12288 + 64*68) * (int)sizeof(float);                   // 66,560 B
    const int sm4 = (5*64*68 + 2*64*16) * (int)sizeof(float);               // 95,232 B

    cudaFuncSetAttribute(k_enc,       cudaFuncAttributeMaxDynamicSharedMemorySize, sm0);
    cudaFuncSetAttribute(k_proj2,     cudaFuncAttributeMaxDynamicSharedMemorySize, sm1);
    cudaFuncSetAttribute(k_gru,       cudaFuncAttributeMaxDynamicSharedMemorySize, sm2);
    cudaFuncSetAttribute(k_attn_cell, cudaFuncAttributeMaxDynamicSharedMemorySize, sm4);

    k_enc<<<256, 256, sm0>>>(obs, W_enc, b_enc);
    k_packW<<<24, 256>>>(Wih_c, Whh_c);
    k_proj2<<<dim3(256,5), 256, sm1>>>(Wq, Wk, Wv, b_v,
                                       Wih_f, bih_f, Wih_b, bih_b);
    k_gru<<<512, 256, sm2>>>(Whh_f, bhh_f, Whh_b, bhh_b, W_hard);
    k_attn_cell<<<256, 512, sm4>>>(hidden, gum, b_hard,
                                   bih_c, bhh_c, out);
}

// round 12
// speedup vs baseline: 1.2326x; 1.2326x over previous
#include <cuda_runtime.h>
#include <cuda_bf16.h>
#include <math.h>
#include <stdint.h>

#define NROWS 16384
#define Tt 15
#define EPSg 1e-10f

typedef unsigned long long u64t;

// ---------------- scratch ----------------
__device__ float g_h[NROWS*64];
__device__ float g_q[NROWS*64];
__device__ float g_k[NROWS*64];
__device__ float g_v[NROWS*64];
// PLAIN layout: [row][gate*64+c]; Cb has bih (+bhh for r,z) folded
__device__ float g_Gf [NROWS*192];
__device__ float g_Cbf[NROWS*192];
__device__ float g_Gb [NROWS*192];
__device__ float g_Cbb[NROWS*192];
__device__ float g_lf[NROWS*2*Tt];
__device__ float g_lb[NROWS*2*Tt];
__device__ float g_Wc[64*3*32*4];

__device__ __forceinline__ float sigm(float x){ return 1.0f/(1.0f+__expf(-x)); }
__device__ __forceinline__ float tanh_(float x){ return 2.0f/(1.0f+__expf(-2.0f*x)) - 1.0f; }

__device__ __forceinline__ u64t pk(float x, float y){
    u64t r; asm("mov.b64 %0,{%1,%2};" : "=l"(r) : "f"(x), "f"(y)); return r;
}
__device__ __forceinline__ float2 up(u64t v){
    float2 r; asm("mov.b64 {%0,%1},%2;" : "=f"(r.x), "=f"(r.y) : "l"(v)); return r;
}
__device__ __forceinline__ void fma2(u64t& d, u64t a, u64t b){
    asm("fma.rn.f32x2 %0,%1,%2,%0;" : "+l"(d) : "l"(a), "l"(b));
}
__device__ __forceinline__ int pairpos64(int d, int c){
    return ((d<<5) + (((c>>5)&1)<<4) + (c&15))*2 + ((c>>4)&1);
}
__device__ __forceinline__ uint32_t bfpair(float a, float b){
    __nv_bfloat162 t = __floats2bfloat162_rn(a, b);
    return *(uint32_t*)&t;
}
__device__ __forceinline__ float bfhi(float x){
    return __bfloat162float(__float2bfloat16(x));
}
__device__ __forceinline__ float2 bf2f(uint32_t u){
    __nv_bfloat162 b = *(__nv_bfloat162*)&u;
    return __bfloat1622float2(b);
}
__device__ __forceinline__ void mma16816(float* d, uint32_t a0, uint32_t a1,
                                         uint32_t a2, uint32_t a3,
                                         uint32_t b0, uint32_t b1){
    asm volatile(
      "mma.sync.aligned.m16n8k16.row.col.f32.bf16.bf16.f32 "
      "{%0,%1,%2,%3},{%4,%5,%6,%7},{%8,%9},{%0,%1,%2,%3};"
      : "+f"(d[0]), "+f"(d[1]), "+f"(d[2]), "+f"(d[3])
      : "r"(a0), "r"(a1), "r"(a2), "r"(a3), "r"(b0), "r"(b1));
}

// =====================================================================
// K0: encoder (unchanged)
// =====================================================================
__global__ __launch_bounds__(256)
void k_enc(const float* __restrict__ obs,
           const float* __restrict__ W_enc, const float* __restrict__ b_enc)
{
    extern __shared__ float sm[];
    float* Os = sm;
    float* Wt = sm + 64*68;
    const u64t* Wt64 = (const u64t*)Wt;
    const int tid = threadIdx.x;
    const int rbase = blockIdx.x * 64;
    const int ty = tid >> 4, tx = tid & 15;
    const int r0 = ty * 4;
    int dcol[4];
    #pragma unroll
    for (int k=0;k<4;k++) dcol[k] = tx + ((k>>1)<<5) + ((k&1)<<4);

    for (int idx = tid; idx < 4096; idx += 256) {
        int r = idx >> 6, c = idx & 63;
        Os[r*68+c] = obs[(rbase+r)*64 + c];
        Wt[pairpos64(r, c)] = W_enc[idx];
    }
    __syncthreads();

    u64t acc[4][2];
    #pragma unroll
    for (int i=0;i<4;i++){ acc[i][0]=0ull; acc[i][1]=0ull; }
    for (int dd=0; dd<64; ++dd){
        u64t pa[4];
        #pragma unroll
        for (int i=0;i<4;i++){ float a=Os[(r0+i)*68+dd]; pa[i]=pk(a,a); }
        #pragma unroll
        for (int p=0;p<2;p++){
            u64t w = Wt64[dd*32 + p*16 + tx];
            #pragma unroll
            for (int i=0;i<4;i++) fma2(acc[i][p], pa[i], w);
        }
    }
    #pragma unroll
    for (int i=0;i<4;i++)
        #pragma unroll
        for (int p=0;p<2;p++){
            float2 v = up(acc[i][p]);
            int d0 = dcol[2*p], d1 = dcol[2*p+1];
            g_h[(rbase+r0+i)*64 + d0] = fmaxf(v.x + b_enc[d0], 0.0f);
            g_h[(rbase+r0+i)*64 + d1] = fmaxf(v.y + b_enc[d1], 0.0f);
        }
}

// =====================================================================
// K0b: pack cell weights (unchanged)
// =====================================================================
__global__ __launch_bounds__(256)
void k_packW(const float* __restrict__ Wih_c, const float* __restrict__ Whh_c)
{
    int idx = blockIdx.x * 256 + threadIdx.x;
    if (idx >= 6144) return;
    int dd = idx / 96;
    int rem = idx - dd*96;
    int gate = rem >> 5;
    int c = rem & 31;
    float4 w;
    w.x = Wih_c[(gate*64 + c     )*64 + dd];
    w.y = Wih_c[(gate*64 + c + 32)*64 + dd];
    w.z = Whh_c[(gate*64 + c     )*64 + dd];
    w.w = Whh_c[(gate*64 + c + 32)*64 + dd];
    ((float4*)g_Wc)[idx] = w;
}

// =====================================================================
// K1: projections -> plain layout; Cb folds bih (+bhh for r,z gates)
// =====================================================================
__global__ __launch_bounds__(256)
void k_proj2(const float* __restrict__ Wq, const float* __restrict__ Wk,
             const float* __restrict__ Wv, const float* __restrict__ b_v,
             const float* __restrict__ Wih_f, const float* __restrict__ bih_f,
             const float* __restrict__ Wih_b, const float* __restrict__ bih_b,
             const float* __restrict__ bhh_f, const float* __restrict__ bhh_b)
{
    extern __shared__ float sm[];
    float* Hs = sm;
    float* Wt = sm + 64*68;
    const u64t* Wt64 = (const u64t*)Wt;
    const int tid = threadIdx.x;
    const int rbase = blockIdx.x * 64;
    const int gy = blockIdx.y;
    const int ty = tid >> 4, tx = tid & 15;
    const int r0 = ty * 4;
    int dcol[4];
    #pragma unroll
    for (int k=0;k<4;k++) dcol[k] = tx + ((k>>1)<<5) + ((k&1)<<4);

    for (int idx = tid; idx < 4096; idx += 256) {
        int r = idx >> 6, c = idx & 63;
        Hs[r*68+c] = g_h[(rbase+r)*64 + c];
    }

    for (int j = 0; j < 3; ++j){
        const float* Wsrc=nullptr; const float* bias=nullptr; const float* bhh=nullptr;
        float* dst=nullptr; int mode; int doRelu=0; int gate=j;
        if (gy==0){
            mode=0;
            if (j==0){ Wsrc=Wq; dst=g_q; }
            else if (j==1){ Wsrc=Wk; dst=g_k; }
            else { Wsrc=Wv; dst=g_v; bias=b_v; doRelu=1; }
        } else if (gy==1){ mode=1; Wsrc=Wih_f; dst=g_Cbf; bias=bih_f; bhh=bhh_f; }
        else if   (gy==2){ mode=2; Wsrc=Wih_f; dst=g_Gf; }
        else if   (gy==3){ mode=1; Wsrc=Wih_b; dst=g_Cbb; bias=bih_b; bhh=bhh_b; }
        else              { mode=2; Wsrc=Wih_b; dst=g_Gb; }
        const int colBase = gate*64;

        __syncthreads();
        for (int idx = tid; idx < 4096; idx += 256){
            int hi = idx >> 6, lo = idx & 63;
            if (mode==0) Wt[pairpos64(hi, lo)] = Wsrc[idx];
            else {
                int off = (colBase+hi)*128 + lo + (mode==2 ? 64 : 0);
                Wt[pairpos64(lo, hi)] = Wsrc[off];
            }
        }
        __syncthreads();

        u64t acc[4][2];
        #pragma unroll
        for (int i=0;i<4;i++){ acc[i][0]=0ull; acc[i][1]=0ull; }
        for (int dd=0; dd<64; ++dd){
            u64t pa[4];
            #pragma unroll
            for (int i=0;i<4;i++){ float a=Hs[(r0+i)*68+dd]; pa[i]=pk(a,a); }
            #pragma unroll
            for (int p=0;p<2;p++){
                u64t w = Wt64[dd*32 + p*16 + tx];
                #pragma unroll
                for (int i=0;i<4;i++) fma2(acc[i][p], pa[i], w);
            }
        }

        #pragma unroll
        for (int i=0;i<4;i++)
            #pragma unroll
            for (int p=0;p<2;p++){
                float2 v = up(acc[i][p]);
                #pragma unroll
                for (int h=0;h<2;h++){
                    int d = dcol[2*p+h];
                    float vv = (h ? v.y : v.x);
                    if (mode==0){
                        if (bias) vv += bias[d];
                        if (doRelu) vv = fmaxf(vv, 0.0f);
                        dst[(rbase+r0+i)*64 + d] = vv;
                    } else {
                        if (mode==1){
                            vv += bias[colBase+d];
                            if (gate < 2) vv += bhh[colBase+d];
                        }
                        dst[(rbase+r0+i)*192 + colBase + d] = vv;
                    }
                }
            }
    }
}

// =====================================================================
// K2: GRU via mma.sync m16n8k16 bf16 (3-term split).
// grid 512 (256 fwd-tiles + 256 bwd), block 128 (4 warps), 2 CTAs/SM.
// Warp owns 16 rows (one batch). D-frag == A-frag layout -> h stays in
// registers as bf16 hi/lo A fragments; zero syncs in the step loop.
// Tiles: jn 0..7 = r-gate, 8..15 = z, 16..23 = n, 24 = logits (W_hard).
// D init: r/z = Cb+G (biases folded); n = bhh_n; logits = 0.
// smem: per-lane B fragments [split(2)][kt(4)][jn(25)][lane(32)] u64 = 50KB
// =====================================================================
__global__ __launch_bounds__(128,2)
void k_gru_mma(const float* __restrict__ Whh_f, const float* __restrict__ Whh_b,
               const float* __restrict__ bhh_f, const float* __restrict__ bhh_b,
               const float* __restrict__ W_hard)
{
    extern __shared__ u64t Bsm[];   // 6400 u64
    const int tid = threadIdx.x;
    const int w = tid >> 5, lane = tid & 31;
    const int g = lane >> 2, tg = lane & 3;
    const int fwd = (blockIdx.x < 256);
    const int rbase = (blockIdx.x & 255) * 64;
    const float* Whh = fwd ? Whh_f : Whh_b;
    const float* bhh = fwd ? bhh_f : bhh_b;
    const float* Gg  = fwd ? g_Gf  : g_Gb;
    const float* Cbg = fwd ? g_Cbf : g_Cbb;
    u64t* lout = (u64t*)(fwd ? g_lf : g_lb);
    const int whb = fwd ? 0 : 64;

    // ---- build per-lane B fragments (hi/lo bf16) ----
    for (int idx = tid; idx < 6400; idx += 128){
        int ln = idx & 31, f = idx >> 5;
        int split = f / 100, rem = f - split*100;
        int kt = rem / 25, jn = rem - kt*25;
        int gg = ln >> 2, tt = ln & 3;
        float w0,w1,w2,w3;
        if (jn < 24){
            const float* src = Whh + (8*jn + gg)*64 + 16*kt;
            w0 = src[2*tt]; w1 = src[2*tt+1]; w2 = src[8+2*tt]; w3 = src[9+2*tt];
        } else if (gg < 2){
            int kb = whb + 16*kt;
            w0 = W_hard[(kb+2*tt  )*2 + gg];
            w1 = W_hard[(kb+2*tt+1)*2 + gg];
            w2 = W_hard[(kb+8+2*tt  )*2 + gg];
            w3 = W_hard[(kb+9+2*tt  )*2 + gg];
        } else { w0=w1=w2=w3=0.f; }
        if (split){
            w0 -= bfhi(w0); w1 -= bfhi(w1); w2 -= bfhi(w2); w3 -= bfhi(w3);
        }
        uint32_t b0 = bfpair(w0,w1), b1 = bfpair(w2,w3);
        Bsm[idx] = ((u64t)b1 << 32) | (u64t)b0;
    }
    __syncthreads();

    const int rowbase = rbase + w*16;
    const int rg0 = rowbase + g, rg8 = rg0 + 8;
    const float* cb0p = Cbg + (size_t)rg0*192 + 2*tg;
    const float* cb8p = Cbg + (size_t)rg8*192 + 2*tg;
    const float* Gbase = Gg + (size_t)rowbase*192 + 2*tg;
    const u64t* Bw = Bsm + lane;

    // bhh_n per-lane constants: tile j cols 8j+2tg, +1
    float bnv[8][2];
    #pragma unroll
    for (int j=0;j<8;j++){
        float2 v = *(const float2*)&bhh[128 + 8*j + 2*tg];
        bnv[j][0] = v.x; bnv[j][1] = v.y;
    }

    float D[25][4];
    uint32_t Ahi[4][4], Alo[4][4];
    #pragma unroll
    for (int kt=0;kt<4;kt++)
        #pragma unroll
        for (int x=0;x<4;x++){ Ahi[kt][x]=0u; Alo[kt][x]=0u; }

    #pragma unroll 1
    for (int ti = 0; ti < Tt; ++ti){
        const int t = fwd ? ti : (Tt-1-ti);
        const int jl0 = t + (t >= g);
        const int jl8 = t + (t >= g+8);
        const float* g0p = Gbase + jl0*192;
        const float* g8p = Gbase + jl8*192;

        // ---- D init ----
        #pragma unroll
        for (int jj=0; jj<16; ++jj){             // r (0..7) + z (8..15): cols 8*jj
            float2 c0 = *(const float2*)(cb0p + 8*jj);
            float2 e0 = *(const float2*)(g0p  + 8*jj);
            float2 c8 = *(const float2*)(cb8p + 8*jj);
            float2 e8 = *(const float2*)(g8p  + 8*jj);
            D[jj][0] = c0.x + e0.x; D[jj][1] = c0.y + e0.y;
            D[jj][2] = c8.x + e8.x; D[jj][3] = c8.y + e8.y;
        }
        #pragma unroll
        for (int j=0;j<8;j++){
            D[16+j][0] = bnv[j][0]; D[16+j][1] = bnv[j][1];
            D[16+j][2] = bnv[j][0]; D[16+j][3] = bnv[j][1];
        }
        D[24][0]=0.f; D[24][1]=0.f; D[24][2]=0.f; D[24][3]=0.f;

        // ---- GEMM: gh += h_{ti-1} @ Whh^T (+ logits tile) ----
        if (ti){
            #pragma unroll
            for (int jn=0; jn<25; ++jn){
                #pragma unroll
                for (int kt=0; kt<4; ++kt){
                    u64t bh = Bw[((    kt)*25 + jn)*32];
                    u64t bl = Bw[((4 + kt)*25 + jn)*32];
                    uint32_t bh0 = (uint32_t)bh, bh1 = (uint32_t)(bh>>32);
                    uint32_t bl0 = (uint32_t)bl, bl1 = (uint32_t)(bl>>32);
                    mma16816(D[jn], Ahi[kt][0],Ahi[kt][1],Ahi[kt][2],Ahi[kt][3], bh0,bh1);
                    mma16816(D[jn], Alo[kt][0],Alo[kt][1],Alo[kt][2],Alo[kt][3], bh0,bh1);
                    mma16816(D[jn], Ahi[kt][0],Ahi[kt][1],Ahi[kt][2],Ahi[kt][3], bl0,bl1);
                }
            }
            if (tg == 0){
                int tp = fwd ? (ti-1) : (Tt-ti);
                lout[(size_t)rg0*Tt + tp] = pk(D[24][0], D[24][1]);
                lout[(size_t)rg8*Tt + tp] = pk(D[24][2], D[24][3]);
            }
        }

        // ---- gate epilogue -> h_ti -> A fragments ----
        #pragma unroll
        for (int j=0;j<8;++j){
            float2 cn0 = *(const float2*)(cb0p + 128 + 8*j);
            float2 en0 = *(const float2*)(g0p  + 128 + 8*j);
            float2 cn8 = *(const float2*)(cb8p + 128 + 8*j);
            float2 en8 = *(const float2*)(g8p  + 128 + 8*j);
            int kt = j >> 1, px = (j & 1) * 2;
            float2 hA = bf2f(Ahi[kt][px]),   lA = bf2f(Alo[kt][px]);
            float2 hB = bf2f(Ahi[kt][px+1]), lB = bf2f(Alo[kt][px+1]);
            float ho0 = hA.x + lA.x, ho1 = hA.y + lA.y;
            float ho2 = hB.x + lB.x, ho3 = hB.y + lB.y;
            float r0 = sigm(D[j][0]),  r1 = sigm(D[j][1]);
            float r2 = sigm(D[j][2]),  r3 = sigm(D[j][3]);
            float z0 = sigm(D[j+8][0]), z1 = sigm(D[j+8][1]);
            float z2 = sigm(D[j+8][2]), z3 = sigm(D[j+8][3]);
            float n0 = tanh_(cn0.x + en0.x + r0*D[j+16][0]);
            float n1 = tanh_(cn0.y + en0.y + r1*D[j+16][1]);
            float n2 = tanh_(cn8.x + en8.x + r2*D[j+16][2]);
            float n3 = tanh_(cn8.y + en8.y + r3*D[j+16][3]);
            float h0 = (1.f - z0)*n0 + z0*ho0;
            float h1 = (1.f - z1)*n1 + z1*ho1;
            float h2 = (1.f - z2)*n2 + z2*ho2;
            float h3 = (1.f - z3)*n3 + z3*ho3;
            Ahi[kt][px]   = bfpair(h0, h1);
            Alo[kt][px]   = bfpair(h0 - bfhi(h0), h1 - bfhi(h1));
            Ahi[kt][px+1] = bfpair(h2, h3);
            Alo[kt][px+1] = bfpair(h2 - bfhi(h2), h3 - bfhi(h3));
        }
    }

    // ---- flush: logits of h_{Tt-1} ----
    {
        float dl[4] = {0.f,0.f,0.f,0.f};
        #pragma unroll
        for (int kt=0; kt<4; ++kt){
            u64t bh = Bw[((    kt)*25 + 24)*32];
            u64t bl = Bw[((4 + kt)*25 + 24)*32];
            uint32_t bh0 = (uint32_t)bh, bh1 = (uint32_t)(bh>>32);
            uint32_t bl0 = (uint32_t)bl, bl1 = (uint32_t)(bl>>32);
            mma16816(dl, Ahi[kt][0],Ahi[kt][1],Ahi[kt][2],Ahi[kt][3], bh0,bh1);
            mma16816(dl, Alo[kt][0],Alo[kt][1],Alo[kt][2],Alo[kt][3], bh0,bh1);
            mma16816(dl, Ahi[kt][0],Ahi[kt][1],Ahi[kt][2],Ahi[kt][3], bl0,bl1);
        }
        if (tg == 0){
            int tp = fwd ? (Tt-1) : 0;
            lout[(size_t)rg0*Tt + tp] = pk(dl[0], dl[1]);
            lout[(size_t)rg8*Tt + tp] = pk(dl[2], dl[3]);
        }
    }
}

// =====================================================================
// K3: gumbel + attention + final GRU cell (unchanged from passing R8)
// =====================================================================
__global__ __launch_bounds__(512,2)
void k_attn_cell(const float* __restrict__ hidden,
                 const float* __restrict__ gum,
                 const float* __restrict__ b_hard,
                 const float* __restrict__ bih_c, const float* __restrict__ bhh_c,
                 float* __restrict__ out)
{
    extern __shared__ float sm[];
    float* qs  = sm;
    float* ks_ = qs  + 64*68;
    float* vs  = ks_ + 64*68;
    float* hds = vs  + 64*68;
    float* xs  = hds + 64*68;
    float* hw  = xs  + 64*68;
    float* sc  = hw  + 64*16;
    const int tid = threadIdx.x;
    const int rbase = blockIdx.x * 64;

    for (int idx=tid; idx<1024; idx+=512){
        int r=idx>>4, c4=idx&15;
        ((float4*)qs )[r*17+c4] = ((const float4*)g_q)[(rbase+r)*16+c4];
        ((float4*)ks_)[r*17+c4] = ((const float4*)g_k)[(rbase+r)*16+c4];
        ((float4*)vs )[r*17+c4] = ((const float4*)g_v)[(rbase+r)*16+c4];
        ((float4*)hds)[r*17+c4] = ((const float4*)hidden)[(rbase+r)*16+c4];
    }
    {
        const float bh0 = b_hard[0], bh1 = b_hard[1];
        for (int idx=tid; idx<64*Tt; idx+=512){
            int r=idx/Tt, t=idx-r*Tt;
            int row = rbase + r;
            float L0 = g_lf[row*(2*Tt)+2*t]   + g_lb[row*(2*Tt)+2*t]   + bh0;
            float L1 = g_lf[row*(2*Tt)+2*t+1] + g_lb[row*(2*Tt)+2*t+1] + bh1;
            int gi = (row*Tt + t)*2;
            float u0 = gum[gi], u1 = gum[gi+1];
            float gg0 = -logf(-logf(u0+EPSg)+EPSg);
            float gg1 = -logf(-logf(u1+EPSg)+EPSg);
            float dlt = ((L1+gg1)-(L0+gg0)) * 100.0f;
            hw[r*16+t] = 1.0f/(1.0f+__expf(-dlt));
        }
    }
    __syncthreads();

    {
        int rp = tid>>3, qq = tid&7;
        #pragma unroll
        for (int s2=0; s2<2; ++s2){
            int t = qq + 8*s2;
            if (t < Tt){
                int ii = rp & 15;
                int jl = (rp & 48) + t + (t>=ii ? 1 : 0);
                float dot=0.f;
                #pragma unroll 8
                for (int d=0; d<64; ++d) dot += qs[rp*68+d]*ks_[jl*68+d];
                sc[rp*16+t] = dot*0.125f;
            }
        }
    }
    __syncthreads();
    if (tid < 64){
        int r=tid;
        float m=-1e30f;
        #pragma unroll
        for (int t=0;t<Tt;t++) m = fmaxf(m, sc[r*16+t]);
        float e[Tt]; float ssum=0.f;
        #pragma unroll
        for (int t=0;t<Tt;t++){ e[t]=__expf(sc[r*16+t]-m); ssum+=e[t]; }
        float inv = 1.0f/ssum;
        #pragma unroll
        for (int t=0;t<Tt;t++) sc[r*16+t] = e[t]*inv*hw[r*16+t];
    }
    __syncthreads();
    for (int idx=tid; idx<4096; idx+=512){
        int r=idx>>6, d=idx&63;
        int ii = r & 15, rb2 = r & 48;
        float x=0.f;
        #pragma unroll
        for (int t=0;t<Tt;t++){
            int jl = rb2 + t + (t>=ii ? 1 : 0);
            x += vs[jl*68+d]*sc[r*16+t];
        }
        xs[r*68+d]=x;
    }
    __syncthreads();

    const int wid = tid >> 5, lane = tid & 31;
    const int r0 = wid * 4;
    const float4* Wc4 = (const float4*)g_Wc;

    float2 aR[4], aZ[4], aI[4], aH[4];
    #pragma unroll
    for (int i=0;i<4;i++){
        aR[i]=make_float2(0.f,0.f); aZ[i]=make_float2(0.f,0.f);
        aI[i]=make_float2(0.f,0.f); aH[i]=make_float2(0.f,0.f);
    }
    #pragma unroll 2
    for (int dd=0; dd<64; ++dd){
        float4 w0 = Wc4[(dd*3+0)*32 + lane];
        float4 w1 = Wc4[(dd*3+1)*32 + lane];
        float4 w2 = Wc4[(dd*3+2)*32 + lane];
        #pragma unroll
        for (int i=0;i<4;i++){
            float x = xs [(r0+i)*68 + dd];
            float h = hds[(r0+i)*68 + dd];
            aR[i].x += x*w0.x + h*w0.z;  aR[i].y += x*w0.y + h*w0.w;
            aZ[i].x += x*w1.x + h*w1.z;  aZ[i].y += x*w1.y + h*w1.w;
            aI[i].x += x*w2.x;           aI[i].y += x*w2.y;
            aH[i].x += h*w2.z;           aH[i].y += h*w2.w;
        }
    }
    float brc_lo = bih_c[lane]      + bhh_c[lane];
    float brc_hi = bih_c[lane+32]   + bhh_c[lane+32];
    float bzc_lo = bih_c[64+lane]   + bhh_c[64+lane];
    float bzc_hi = bih_c[96+lane]   + bhh_c[96+lane];
    float bni_lo = bih_c[128+lane],  bni_hi = bih_c[160+lane];
    float bnh_lo = bhh_c[128+lane],  bnh_hi = bhh_c[160+lane];
    #pragma unroll
    for (int i=0;i<4;i++){
        int rl = r0+i;
        float ho_lo = hds[rl*68 + lane];
        float ho_hi = hds[rl*68 + 32 + lane];
        float r_lo = sigm(aR[i].x + brc_lo);
        float r_hi = sigm(aR[i].y + brc_hi);
        float z_lo = sigm(aZ[i].x + bzc_lo);
        float z_hi = sigm(aZ[i].y + bzc_hi);
        float n_lo = tanh_(aI[i].x + bni_lo + r_lo*(aH[i].x + bnh_lo));
        float n_hi = tanh_(aI[i].y + bni_hi + r_hi*(aH[i].y + bnh_hi));
        out[(rbase+rl)*64 + lane]      = (1.0f - z_lo)*n_lo + z_lo*ho_lo;
        out[(rbase+rl)*64 + 32 + lane] = (1.0f - z_hi)*n_hi + z_hi*ho_hi;
    }
}

// =====================================================================
extern "C" void kernel_launch(void* const* d_in, const int* in_sizes, int n_in,
                              void* d_out, int out_size)
{
    (void)in_sizes; (void)n_in; (void)out_size;
    const float* obs    = (const float*)d_in[0];
    const float* hidden = (const float*)d_in[1];
    const float* gum    = (const float*)d_in[2];
    const float* W_enc  = (const float*)d_in[3];
    const float* b_enc  = (const float*)d_in[4];
    const float* Wih_f  = (const float*)d_in[5];
    const float* Whh_f  = (const float*)d_in[6];
    const float* bih_f  = (const float*)d_in[7];
    const float* bhh_f  = (const float*)d_in[8];
    const float* Wih_b  = (const float*)d_in[9];
    const float* Whh_b  = (const float*)d_in[10];
    const float* bih_b  = (const float*)d_in[11];
    const float* bhh_b  = (const float*)d_in[12];
    const float* W_hard = (const float*)d_in[13];
    const float* b_hard = (const float*)d_in[14];
    const float* Wq     = (const float*)d_in[15];
    const float* Wk     = (const float*)d_in[16];
    const float* Wv     = (const float*)d_in[17];
    const float* b_v    = (const float*)d_in[18];
    const float* Wih_c  = (const float*)d_in[19];
    const float* Whh_c  = (const float*)d_in[20];
    const float* bih_c  = (const float*)d_in[21];
    const float* bhh_c  = (const float*)d_in[22];
    float* out = (float*)d_out;

    const int sm0 = (64*68 + 4096) * (int)sizeof(float);   // 33,792 B
    const int sm1 = (64*68 + 4096) * (int)sizeof(float);   // 33,792 B
    const int sm2 = 6400 * (int)sizeof(u64t);              // 51,200 B
    const int sm4 = (5*64*68 + 2*64*16) * (int)sizeof(float); // 95,232 B

    cudaFuncSetAttribute(k_enc,       cudaFuncAttributeMaxDynamicSharedMemorySize, sm0);
    cudaFuncSetAttribute(k_proj2,     cudaFuncAttributeMaxDynamicSharedMemorySize, sm1);
    cudaFuncSetAttribute(k_gru_mma,   cudaFuncAttributeMaxDynamicSharedMemorySize, sm2);
    cudaFuncSetAttribute(k_attn_cell, cudaFuncAttributeMaxDynamicSharedMemorySize, sm4);

    k_enc<<<256, 256, sm0>>>(obs, W_enc, b_enc);
    k_packW<<<24, 256>>>(Wih_c, Whh_c);
    k_proj2<<<dim3(256,5), 256, sm1>>>(Wq, Wk, Wv, b_v,
                                       Wih_f, bih_f, Wih_b, bih_b,
                                       bhh_f, bhh_b);
    k_gru_mma<<<512, 128, sm2>>>(Whh_f, Whh_b, bhh_f, bhh_b, W_hard);
    k_attn_cell<<<256, 512, sm4>>>(hidden, gum, b_hard, bih_c, bhh_c, out);
}